// round 10
// baseline (speedup 1.0000x reference)
#include <cuda_runtime.h>
#include <cuda_bf16.h>

#define IN_DIM   512
#define BATCH    8192
#define GRID_NUM 48
#define NCOEF    (GRID_NUM + 3)   // 51
#define NKNOT    (GRID_NUM + 1)   // 49
#define TILE     64               // dims per block -> 8 dim-tiles
#define THREADS  256
#define NBLOCKS  1184             // 148 SMs x 8 blocks: exactly one wave
#define NRG      148              // row-group columns per dim-tile
#define NRG_TOT  2048             // BATCH/4
#define CELL_LO  24               // x in [0,1) -> t in [24,48)
#define NCELL_S  24               // staged cells 24..47
#define CPC      6                // cells per prep chunk
#define COLPC    9                // coef cols per chunk (cells c..c+5 need cols c..c+8)

__global__ __launch_bounds__(THREADS, 8) void bspline_fused_kernel(
    const float* __restrict__ x,
    const float* __restrict__ grid,
    const float* __restrict__ coef,
    float* __restrict__ y)
{
    __shared__ float4 s_quad[NCELL_S * TILE];   // exactly 24 KB
    // 2.25 KB staging buffer aliased into the last 6 quad rows (written only by chunk 3,
    // and only after all buffer reads of that chunk completed into registers).
    float* s_buf = reinterpret_cast<float*>(s_quad + 18 * TILE);

    const int tid  = threadIdx.x;
    const int bid  = blockIdx.x;
    const int dim0 = (bid & 7) * TILE;
    const int rg0  = bid >> 3;                  // 0..147

    // ---- Build quad table in 4 chunks (smem stays at 24 KB) ----
    #pragma unroll
    for (int ch = 0; ch < 4; ++ch) {
        const int c0 = CELL_LO + ch * CPC;      // first coef column this chunk
        // Stage 64 dims x 9 cols (contiguous 9-float runs per dim).
        #pragma unroll
        for (int k = tid; k < TILE * COLPC; k += THREADS) {
            int d = k / COLPC, c = k - d * COLPC;
            s_buf[k] = coef[(dim0 + d) * NCOEF + c0 + c];
        }
        __syncthreads();
        // Pull this thread's inputs into registers (stride-9 LDS: conflict-free).
        float r[2][4];
        #pragma unroll
        for (int qq = 0; qq < 2; ++qq) {
            int k = tid + qq * THREADS;
            if (k < TILE * CPC) {               // 384 items: threads 0-127 do 2
                int cl = k >> 6, d = k & (TILE - 1);
                const float* p = s_buf + d * COLPC + cl;
                r[qq][0] = p[0]; r[qq][1] = p[1]; r[qq][2] = p[2]; r[qq][3] = p[3];
            }
        }
        __syncthreads();
        // Compute + write quads (STS.128 phases: consecutive-d lanes, conflict-free).
        #pragma unroll
        for (int qq = 0; qq < 2; ++qq) {
            int k = tid + qq * THREADS;
            if (k < TILE * CPC) {
                int cl = k >> 6, d = k & (TILE - 1);
                float c0f = r[qq][0], c1 = r[qq][1], c2 = r[qq][2], c3 = r[qq][3];
                float4 a;
                a.x = (c0f + 4.0f * c1 + c2) * (1.0f / 6.0f);
                a.y = (c2 - c0f) * 0.5f;
                a.z = (c0f - 2.0f * c1 + c2) * 0.5f;
                a.w = (c3 - c0f + 3.0f * (c1 - c2)) * (1.0f / 6.0f);
                s_quad[(ch * CPC + cl) * TILE + d] = a;
            }
        }
        // No extra sync: next stage writes s_buf (rows 18-23), disjoint from this
        // chunk's quad rows for ch<3; ch==3 has no next iteration.
    }

    const int d    = tid & (TILE - 1);
    const int rofs = tid >> 6;                  // 0..3
    const int col  = dim0 + d;
    const float glo  = grid[col * NKNOT];
    const float ghi  = grid[col * NKNOT + GRID_NUM];
    const float invh = (float)GRID_NUM / (ghi - glo);

    __syncthreads();                            // table complete

    const int idx0    = (rg0 * 4 + rofs) * IN_DIM + col;
    const int max_idx = ((NRG_TOT - 1) * 4 + rofs) * IN_DIM + col;
    const int K_OFF   = NRG * 4 * IN_DIM;       // per row-group-step offset

    // 3 full q=4 groups: k=0..11 always in-range (147 + 11*148 = 1775 < 2048).
    #pragma unroll
    for (int it = 0; it < 3; ++it) {
        const int base = idx0 + it * 4 * K_OFF;
        float xv[4], res[4];
        #pragma unroll
        for (int q = 0; q < 4; ++q)
            xv[q] = x[base + q * K_OFF];
        #pragma unroll
        for (int q = 0; q < 4; ++q) {
            float t = (xv[q] - glo) * invh;
            int cell = (int)t;
            cell = max(0, min(cell, GRID_NUM - 1));
            float u = t - (float)cell;
            int cs = cell - CELL_LO;
            float4 a;
            if ((unsigned)cs < (unsigned)NCELL_S) {
                a = s_quad[cs * TILE + d];      // conflict-free LDS.128
            } else {                            // never taken for in-range x
                const float* c = coef + col * NCOEF + cell;
                float c0f = c[0], c1 = c[1], c2 = c[2], c3 = c[3];
                a.x = (c0f + 4.0f * c1 + c2) * (1.0f / 6.0f);
                a.y = (c2 - c0f) * 0.5f;
                a.z = (c0f - 2.0f * c1 + c2) * 0.5f;
                a.w = (c3 - c0f + 3.0f * (c1 - c2)) * (1.0f / 6.0f);
            }
            res[q] = fmaf(fmaf(fmaf(a.w, u, a.z), u, a.y), u, a.x);
        }
        #pragma unroll
        for (int q = 0; q < 4; ++q)
            y[base + q * K_OFF] = res[q];
    }

    // Tail: k=12 in-range (147+1776=1923); k=13 clamped (duplicate rows, identical values).
    {
        const int i12 = idx0 + 12 * K_OFF;
        const int i13 = min(idx0 + 13 * K_OFF, max_idx);
        float xv[2], res[2];
        xv[0] = x[i12];
        xv[1] = x[i13];
        #pragma unroll
        for (int q = 0; q < 2; ++q) {
            float t = (xv[q] - glo) * invh;
            int cell = (int)t;
            cell = max(0, min(cell, GRID_NUM - 1));
            float u = t - (float)cell;
            int cs = cell - CELL_LO;
            float4 a;
            if ((unsigned)cs < (unsigned)NCELL_S) {
                a = s_quad[cs * TILE + d];
            } else {
                const float* c = coef + col * NCOEF + cell;
                float c0f = c[0], c1 = c[1], c2 = c[2], c3 = c[3];
                a.x = (c0f + 4.0f * c1 + c2) * (1.0f / 6.0f);
                a.y = (c2 - c0f) * 0.5f;
                a.z = (c0f - 2.0f * c1 + c2) * 0.5f;
                a.w = (c3 - c0f + 3.0f * (c1 - c2)) * (1.0f / 6.0f);
            }
            res[q] = fmaf(fmaf(fmaf(a.w, u, a.z), u, a.y), u, a.x);
        }
        y[i12] = res[0];
        y[i13] = res[1];
    }
}

extern "C" void kernel_launch(void* const* d_in, const int* in_sizes, int n_in,
                              void* d_out, int out_size) {
    const float* x    = (const float*)d_in[0];
    const float* grid = (const float*)d_in[1];
    const float* coef = (const float*)d_in[2];
    float* y = (float*)d_out;

    bspline_fused_kernel<<<NBLOCKS, THREADS>>>(x, grid, coef, y);
}

// round 12
// speedup vs baseline: 1.0446x; 1.0446x over previous
#include <cuda_runtime.h>
#include <cuda_bf16.h>

#define IN_DIM   512
#define BATCH    8192
#define GRID_NUM 48
#define NCOEF    (GRID_NUM + 3)   // 51
#define NKNOT    (GRID_NUM + 1)   // 49
#define TILE     64               // dims per block -> 8 dim-tiles
#define THREADS  256
#define NBLOCKS  888              // 148 SMs x 6 blocks: one wave (proven best config)
#define NRGCOL   111              // row-slot columns per dim-tile (888/8)
#define NSLOT    1024             // BATCH/8 row-slots per dim-tile
#define CELL_LO  24               // x in [0,1) -> t in [24,48)
#define NCELL_S  24
#define NCOL_S   27               // coef cols 24..50

// Cold path: recompute quad from global coef (never taken for in-range x).
__device__ __noinline__ float eval_cold(float tf, const float* __restrict__ coef, int col) {
    float t = tf + (float)CELL_LO;
    int cell = max(0, min(__float2int_rd(t), GRID_NUM - 1));
    float u = t - (float)cell;
    const float* p = coef + col * NCOEF + cell;
    float c0 = p[0], c1 = p[1], c2 = p[2], c3 = p[3];
    float ax = (c0 + 4.0f * c1 + c2) * (1.0f / 6.0f);
    float ay = (c2 - c0) * 0.5f;
    float az = (c0 - 2.0f * c1 + c2) * 0.5f;
    float aw = (c3 - c0 + 3.0f * (c1 - c2)) * (1.0f / 6.0f);
    return fmaf(fmaf(fmaf(aw, u, az), u, ay), u, ax);
}

__device__ __forceinline__ float eval_hot(float xv, float A, float B,
                                          const float4* __restrict__ tab,
                                          const float* __restrict__ coef, int col) {
    float tf = fmaf(xv, A, B);                 // t - 24
    int cs = __float2int_rd(tf);
    if (__builtin_expect((unsigned)cs < (unsigned)NCELL_S, 1)) {
        float u = tf - (float)cs;
        float4 a = tab[cs * 32];               // conflict-free LDS.128
        return fmaf(fmaf(fmaf(a.w, u, a.z), u, a.y), u, a.x);
    }
    return eval_cold(tf, coef, col);
}

__global__ __launch_bounds__(THREADS, 6) void bspline_fused_kernel(
    const float* __restrict__ x,
    const float* __restrict__ grid,
    const float* __restrict__ coef,
    float* __restrict__ y)
{
    __shared__ float4 s_e[NCELL_S * 32];       // even dims: 12 KB
    __shared__ float4 s_o[NCELL_S * 32];       // odd  dims: 12 KB
    __shared__ float  s_c[TILE * NCOL_S];      // staging:  6.75 KB

    const int tid  = threadIdx.x;
    const int bid  = blockIdx.x;
    const int dim0 = (bid & 7) * TILE;
    const int cgrp = bid >> 3;                 // 0..110 row-slot column

    // Stage coef cols 24..50 for 64 dims (contiguous 27-float runs, coalesced).
    for (int k = tid; k < TILE * NCOL_S; k += THREADS) {
        int d = k / NCOL_S, cc = k - d * NCOL_S;
        s_c[k] = coef[(dim0 + d) * NCOEF + CELL_LO + cc];
    }
    __syncthreads();

    // Build split quad tables (s_c reads stride 27: conflict-free).
    for (int k = tid; k < NCELL_S * TILE; k += THREADS) {
        int cell = k >> 6, d = k & (TILE - 1);
        const float* p = s_c + d * NCOL_S + cell;
        float c0 = p[0], c1 = p[1], c2 = p[2], c3 = p[3];
        float4 a;
        a.x = (c0 + 4.0f * c1 + c2) * (1.0f / 6.0f);
        a.y = (c2 - c0) * 0.5f;
        a.z = (c0 - 2.0f * c1 + c2) * 0.5f;
        a.w = (c3 - c0 + 3.0f * (c1 - c2)) * (1.0f / 6.0f);
        ((d & 1) ? s_o : s_e)[cell * 32 + (d >> 1)] = a;
    }

    const int l    = tid & 31;                 // dim-pair lane
    const int rofs = tid >> 5;                 // 0..7 row within slot
    const int colE = dim0 + 2 * l;
    const int colO = colE + 1;

    float loE = grid[colE * NKNOT], hiE = grid[colE * NKNOT + GRID_NUM];
    float loO = grid[colO * NKNOT], hiO = grid[colO * NKNOT + GRID_NUM];
    const float AE = (float)GRID_NUM / (hiE - loE), BE = fmaf(-loE, AE, -(float)CELL_LO);
    const float AO = (float)GRID_NUM / (hiO - loO), BO = fmaf(-loO, AO, -(float)CELL_LO);

    __syncthreads();

    const float2* __restrict__ x2 = (const float2*)x;
    float2* __restrict__ y2 = (float2*)y;
    const float4* pE = s_e + l;
    const float4* pO = s_o + l;

    const int off     = (dim0 >> 1) + l;
    const int idx0    = (cgrp * 8 + rofs) * (IN_DIM / 2) + off;
    const int SSTEP   = NRGCOL * 8 * (IN_DIM / 2);             // 227328
    const int idx_max = ((NSLOT - 1) * 8 + rofs) * (IN_DIM / 2) + off;

    // 10 slots/thread: steps 0..8 always in-range; step 9 clamped
    // (duplicate rows write identical deterministic values).
    #pragma unroll
    for (int it = 0; it < 5; ++it) {
        int i0 = idx0 + (2 * it) * SSTEP;
        int i1 = idx0 + (2 * it + 1) * SSTEP;
        if (it == 4) i1 = min(i1, idx_max);
        float2 xa = x2[i0];
        float2 xb = x2[i1];
        float2 ra, rb;
        ra.x = eval_hot(xa.x, AE, BE, pE, coef, colE);
        ra.y = eval_hot(xa.y, AO, BO, pO, coef, colO);
        rb.x = eval_hot(xb.x, AE, BE, pE, coef, colE);
        rb.y = eval_hot(xb.y, AO, BO, pO, coef, colO);
        y2[i0] = ra;
        y2[i1] = rb;
    }
}

extern "C" void kernel_launch(void* const* d_in, const int* in_sizes, int n_in,
                              void* d_out, int out_size) {
    const float* x    = (const float*)d_in[0];
    const float* grid = (const float*)d_in[1];
    const float* coef = (const float*)d_in[2];
    float* y = (float*)d_out;

    bspline_fused_kernel<<<NBLOCKS, THREADS>>>(x, grid, coef, y);
}